// round 9
// baseline (speedup 1.0000x reference)
#include <cuda_runtime.h>

// FWHT, 4096 rows x 16384 fp32. Persistent CTAs (grid=148, 1/SM), 1024 thr.
// PAIRED-ROW pipeline: each iteration processes rows (rA, rB=rA+148) as two
// independent register streams through two smem work buffers -> 2x ILP in
// every inter-barrier region, 1.5 barriers/row, and LDG prefetch of the next
// pair issued right after each stream's STG frees its registers.
// Per-row dataflow (unchanged, MIO-minimal):
//   P1: regs H16 over bits {13,12,1,0} (float4 LDG; vector lanes = bits 1,0)
//   X1 -> P2: regs H16 over bits {11..8} (same-address writeback)
//   X2 -> P3: regs H16 over bits {7..4}
//   shfl stages over bits {3,2}; scale 2^-7; coalesced STG.
// Swizzle phys(i) = i + 16*(i>>8): injective, 16B-aligned, conflict-free for
// all four smem patterns (verified R5-R8).

#define N_ELEM 16384
#define THREADS 1024
#define BUF_FLOATS 17408   // max phys idx 16383 + 16*63 = 17391
#define GRID 148
#define STEP (2 * GRID)

__device__ __forceinline__ int physz(int i) { return i + ((i >> 8) << 4); }

template <int N>
__device__ __forceinline__ void hadN(float* v) {
#pragma unroll
    for (int s = 1; s < N; s <<= 1) {
#pragma unroll
        for (int i = 0; i < N; i++) {
            if ((i & s) == 0) {
                float a = v[i];
                float b = v[i | s];
                v[i]     = a + b;
                v[i | s] = a - b;
            }
        }
    }
}

__device__ __forceinline__ void load_row(float* v, const float* __restrict__ in,
                                         int row, int t) {
    const float4* __restrict__ p4 =
        reinterpret_cast<const float4*>(in + (size_t)row * N_ELEM + (t << 2));
#pragma unroll
    for (int j = 0; j < 4; j++) {
        float4 f = p4[(size_t)j << 10];
        v[4 * j + 0] = f.x; v[4 * j + 1] = f.y;
        v[4 * j + 2] = f.z; v[4 * j + 3] = f.w;
    }
}

__global__ __launch_bounds__(THREADS, 1)
void fwht_kernel(const float* __restrict__ in, float* __restrict__ out,
                 int nrows) {
    extern __shared__ float sh[];
    float* __restrict__ bufA = sh;
    float* __restrict__ bufB = sh + BUF_FLOATS;
    const int t = threadIdx.x;
    const int l = t & 31;

    // Immediate-foldable bases:
    // P1: phys(j<<12 | t<<2)                = pa  + j*4352
    // P2: phys((t>>8)<<12 | r<<8 | (t&255)) = pb1 + r*272
    // P3: phys((t>>4)<<8  | r<<4 | (t&15))  = pb2 + r*16
    const int pa  = (t << 2) + ((t >> 6) << 4);
    const int pb1 = physz(((t >> 8) << 12) | (t & 255));
    const int b2  = ((t >> 4) << 8) | (t & 15);
    const int pb2 = physz(b2);

    const float s3 = (l & 8) ? -1.0f : 1.0f;
    const float s2 = (l & 4) ? -1.0f : 1.0f;

    int rowA = blockIdx.x;
    int rowB = rowA + GRID;

    float vA[16], vB[16];
    load_row(vA, in, rowA, t);
    if (rowB < nrows) load_row(vB, in, rowB, t);

    while (rowA < nrows) {
        const bool hasB = (rowB < nrows);

        // ---- P1: two independent butterfly chains + STS.128
        hadN<16>(vA);
#pragma unroll
        for (int j = 0; j < 4; j++)
            *reinterpret_cast<float4*>(&bufA[pa + j * 4352]) =
                make_float4(vA[4 * j], vA[4 * j + 1], vA[4 * j + 2], vA[4 * j + 3]);
        if (hasB) {
            hadN<16>(vB);
#pragma unroll
            for (int j = 0; j < 4; j++)
                *reinterpret_cast<float4*>(&bufB[pa + j * 4352]) =
                    make_float4(vB[4 * j], vB[4 * j + 1], vB[4 * j + 2], vB[4 * j + 3]);
        }
        __syncthreads();  // B1: both buffers fully written

        // ---- P2: bits {11..8}; two streams, in-place writeback
#pragma unroll
        for (int r = 0; r < 16; r++) vA[r] = bufA[pb1 + r * 272];
        if (hasB) {
#pragma unroll
            for (int r = 0; r < 16; r++) vB[r] = bufB[pb1 + r * 272];
        }
        hadN<16>(vA);
        if (hasB) hadN<16>(vB);
#pragma unroll
        for (int r = 0; r < 16; r++) bufA[pb1 + r * 272] = vA[r];
        if (hasB) {
#pragma unroll
            for (int r = 0; r < 16; r++) bufB[pb1 + r * 272] = vB[r];
        }
        __syncthreads();  // B2: both buffers rewritten

        // ---- P3 stream A: bits {7..4} + shfl bits {3,2} + STG, then prefetch
#pragma unroll
        for (int r = 0; r < 16; r++) vA[r] = bufA[pb2 + r * 16];
        hadN<16>(vA);
#pragma unroll
        for (int r = 0; r < 16; r++) {
            float q = __shfl_xor_sync(0xffffffffu, vA[r], 8);
            vA[r] = fmaf(s3, vA[r], q);
        }
#pragma unroll
        for (int r = 0; r < 16; r++) {
            float q = __shfl_xor_sync(0xffffffffu, vA[r], 4);
            vA[r] = fmaf(s2, vA[r], q);
        }
        {
            float* __restrict__ pout = out + (size_t)rowA * N_ELEM;
#pragma unroll
            for (int r = 0; r < 16; r++)
                pout[b2 + (r << 4)] = vA[r] * 0.0078125f;
        }
        if (rowA + STEP < nrows) load_row(vA, in, rowA + STEP, t);  // prefetch

        // ---- P3 stream B (covers stream-A prefetch latency), then prefetch
        if (hasB) {
#pragma unroll
            for (int r = 0; r < 16; r++) vB[r] = bufB[pb2 + r * 16];
            hadN<16>(vB);
#pragma unroll
            for (int r = 0; r < 16; r++) {
                float q = __shfl_xor_sync(0xffffffffu, vB[r], 8);
                vB[r] = fmaf(s3, vB[r], q);
            }
#pragma unroll
            for (int r = 0; r < 16; r++) {
                float q = __shfl_xor_sync(0xffffffffu, vB[r], 4);
                vB[r] = fmaf(s2, vB[r], q);
            }
            float* __restrict__ pout = out + (size_t)rowB * N_ELEM;
#pragma unroll
            for (int r = 0; r < 16; r++)
                pout[b2 + (r << 4)] = vB[r] * 0.0078125f;
            if (rowB + STEP < nrows) load_row(vB, in, rowB + STEP, t);
        }
        __syncthreads();  // B3: X2-reads done -> buffers free for next P1

        rowA += STEP;
        rowB += STEP;
    }
}

extern "C" void kernel_launch(void* const* d_in, const int* in_sizes, int n_in,
                              void* d_out, int out_size) {
    const float* phi = (const float*)d_in[0];
    float* out = (float*)d_out;

    const size_t smem = 2 * BUF_FLOATS * sizeof(float);  // 139264 B
    cudaFuncSetAttribute(fwht_kernel,
                         cudaFuncAttributeMaxDynamicSharedMemorySize,
                         (int)smem);

    const int nrows = in_sizes[0] / N_ELEM;  // 4096
    const int grid = nrows < GRID ? nrows : GRID;
    fwht_kernel<<<grid, THREADS, smem>>>(phi, out, nrows);
}